// round 2
// baseline (speedup 1.0000x reference)
#include <cuda_runtime.h>

// Problem constants (fixed shapes from reference setup_inputs)
#define BB      4
#define NPTS    8192
#define SQ      2048
#define CF      64
#define NSAMPLE 32
#define CH_OUT  67      // 3 (xyz) + 64 (features)
#define RADIUS2 0.04f   // 0.2^2

// Scratch: features transposed to [B][N][C] so per-neighbor channel reads are contiguous.
__device__ float g_featT[(size_t)BB * NPTS * CF];

// ---------------------------------------------------------------------------
// Kernel 1: transpose features (B, C, N) -> (B, N, C)
// Standard 32x32 smem tile transpose; grid = (N/32, C/32, B), block = (32, 8).
// ---------------------------------------------------------------------------
__global__ void __launch_bounds__(256) transpose_feat_kernel(const float* __restrict__ feat) {
    __shared__ float tile[32][33];
    const int b  = blockIdx.z;
    const int n0 = blockIdx.x * 32;
    const int c0 = blockIdx.y * 32;
    const float* f  = feat    + (size_t)b * CF * NPTS;
    float*       ft = g_featT + (size_t)b * NPTS * CF;

#pragma unroll
    for (int i = 0; i < 4; i++) {
        int c = c0 + threadIdx.y + i * 8;
        int n = n0 + threadIdx.x;
        tile[threadIdx.y + i * 8][threadIdx.x] = f[(size_t)c * NPTS + n];
    }
    __syncthreads();
#pragma unroll
    for (int i = 0; i < 4; i++) {
        int n = n0 + threadIdx.y + i * 8;
        int c = c0 + threadIdx.x;
        ft[(size_t)n * CF + c] = tile[threadIdx.x][threadIdx.y + i * 8];
    }
}

// ---------------------------------------------------------------------------
// Kernel 2: ball query + group. One warp per query point (b, s).
// 4 warps / block (128 threads). Static smem: 4 * 2112 floats (gather tile,
// 64x33 padded, conflict-free both phases) + 4 * 32 int (neighbor indices).
// ---------------------------------------------------------------------------
#define WARPS_PER_BLOCK 4

__global__ void __launch_bounds__(128) qag_kernel(const float* __restrict__ xyz,
                                                  const float* __restrict__ new_xyz,
                                                  float* __restrict__ out) {
    __shared__ int   sidx[WARPS_PER_BLOCK][NSAMPLE];
    __shared__ float tile[WARPS_PER_BLOCK][64 * 33];  // [c][k] padded

    const int warp = threadIdx.x >> 5;
    const int lane = threadIdx.x & 31;
    const int q    = blockIdx.x * WARPS_PER_BLOCK + warp;   // global query id
    const int b    = q / SQ;
    const int s    = q % SQ;

    // Query point; q2 with exact reference op ordering (no FMA contraction).
    const float* nq = new_xyz + ((size_t)b * SQ + s) * 3;
    const float qx = nq[0], qy = nq[1], qz = nq[2];
    const float q2 = __fadd_rn(__fadd_rn(__fmul_rn(qx, qx), __fmul_rn(qy, qy)),
                               __fmul_rn(qz, qz));

    const float* px = xyz + (size_t)b * NPTS * 3;

    // ------------------- ball query: warp-synchronous scan with early exit ----
    int cnt = 0;
    for (int base = 0; base < NPTS; base += 32) {
        const int n = base + lane;
        const float x = px[n * 3 + 0];
        const float y = px[n * 3 + 1];
        const float z = px[n * 3 + 2];
        // Replicate reference: d2 = (q2 + p2) - 2*qp, all plain fp32 ops.
        const float p2 = __fadd_rn(__fadd_rn(__fmul_rn(x, x), __fmul_rn(y, y)),
                                   __fmul_rn(z, z));
        const float qp = __fadd_rn(__fadd_rn(__fmul_rn(x, qx), __fmul_rn(y, qy)),
                                   __fmul_rn(z, qz));
        const float d2 = __fsub_rn(__fadd_rn(q2, p2), __fmul_rn(2.0f, qp));
        const bool  in = d2 < RADIUS2;

        const unsigned m = __ballot_sync(0xffffffffu, in);
        if (in) {
            const int slot = cnt + __popc(m & ((1u << lane) - 1u));
            if (slot < NSAMPLE) sidx[warp][slot] = n;
        }
        cnt += __popc(m);          // uniform across the warp
        if (cnt >= NSAMPLE) break; // uniform branch
    }
    __syncwarp();

    // Pad with first index; all-zeros if no neighbor at all (matches reference).
    int myidx;
    if (cnt == 0) {
        myidx = 0;
    } else {
        const int c = cnt < NSAMPLE ? cnt : NSAMPLE;
        myidx = sidx[warp][lane < c ? lane : 0];
    }

    // ------------------- grouped_xyz: lane k handles neighbor k --------------
    {
        const float x = px[myidx * 3 + 0];
        const float y = px[myidx * 3 + 1];
        const float z = px[myidx * 3 + 2];
        const size_t obase = ((size_t)b * CH_OUT) * (size_t)SQ * NSAMPLE
                           + (size_t)s * NSAMPLE + lane;
        const size_t chs = (size_t)SQ * NSAMPLE;
        out[obase + 0 * chs] = x - qx;
        out[obase + 1 * chs] = y - qy;
        out[obase + 2 * chs] = z - qz;
    }

    // ------------------- grouped features: coalesced gather via smem tile ----
    // Read 64 contiguous channels per neighbor from transposed features,
    // transpose in smem, store with k innermost (fully coalesced).
    {
        float* t = tile[warp];
        const float* ft = g_featT + (size_t)b * NPTS * CF;
#pragma unroll 8
        for (int k = 0; k < NSAMPLE; k++) {
            const int idxk = __shfl_sync(0xffffffffu, myidx, k);
            const float* src = ft + (size_t)idxk * CF;
            t[lane * 33 + k]        = src[lane];        // c = lane
            t[(lane + 32) * 33 + k] = src[lane + 32];   // c = lane + 32
        }
        __syncwarp();

        const size_t chs = (size_t)SQ * NSAMPLE;
        const size_t fbase = ((size_t)b * CH_OUT + 3) * chs
                           + (size_t)s * NSAMPLE + lane;
#pragma unroll 8
        for (int c = 0; c < CF; c++) {
            out[fbase + (size_t)c * chs] = t[c * 33 + lane];
        }
    }
}

// ---------------------------------------------------------------------------
// Launch
// ---------------------------------------------------------------------------
extern "C" void kernel_launch(void* const* d_in, const int* in_sizes, int n_in,
                              void* d_out, int out_size) {
    const float* xyz      = (const float*)d_in[0];  // (B, N, 3)
    const float* new_xyz  = (const float*)d_in[1];  // (B, S, 3)
    const float* features = (const float*)d_in[2];  // (B, C, N)
    float*       out      = (float*)d_out;          // (B, 67, S, 32)

    (void)in_sizes; (void)n_in; (void)out_size;

    // 1) transpose features into scratch
    dim3 tgrid(NPTS / 32, CF / 32, BB);
    dim3 tblock(32, 8);
    transpose_feat_kernel<<<tgrid, tblock>>>(features);

    // 2) ball query + group: one warp per query
    const int nquery = BB * SQ;                       // 8192
    const int blocks = nquery / WARPS_PER_BLOCK;      // 2048
    qag_kernel<<<blocks, WARPS_PER_BLOCK * 32>>>(xyz, new_xyz, out);
}

// round 3
// speedup vs baseline: 1.7402x; 1.7402x over previous
#include <cuda_runtime.h>

// Problem constants (fixed shapes from reference setup_inputs)
#define BB      4
#define NPTS    8192
#define SQ      2048
#define CF      64
#define NSAMPLE 32
#define CH_OUT  67      // 3 (xyz) + 64 (features)
#define RADIUS2 0.04f   // 0.2^2

// Scratch: features transposed to [B][N][C] so per-neighbor channel reads are contiguous.
__device__ float g_featT[(size_t)BB * NPTS * CF];

// ---------------------------------------------------------------------------
// Kernel 1: transpose features (B, C, N) -> (B, N, C)
// ---------------------------------------------------------------------------
__global__ void __launch_bounds__(256) transpose_feat_kernel(const float* __restrict__ feat) {
    __shared__ float tile[32][33];
    const int b  = blockIdx.z;
    const int n0 = blockIdx.x * 32;
    const int c0 = blockIdx.y * 32;
    const float* f  = feat    + (size_t)b * CF * NPTS;
    float*       ft = g_featT + (size_t)b * NPTS * CF;

#pragma unroll
    for (int i = 0; i < 4; i++) {
        int c = c0 + threadIdx.y + i * 8;
        int n = n0 + threadIdx.x;
        tile[threadIdx.y + i * 8][threadIdx.x] = f[(size_t)c * NPTS + n];
    }
    __syncthreads();
#pragma unroll
    for (int i = 0; i < 4; i++) {
        int n = n0 + threadIdx.y + i * 8;
        int c = c0 + threadIdx.x;
        ft[(size_t)n * CF + c] = tile[threadIdx.x][threadIdx.y + i * 8];
    }
}

// Exact reference arithmetic: d2 = (q2 + p2) - 2*qp, plain fp32 ops, no FMA.
__device__ __forceinline__ bool in_ball(float x, float y, float z,
                                        float qx, float qy, float qz, float q2) {
    const float p2 = __fadd_rn(__fadd_rn(__fmul_rn(x, x), __fmul_rn(y, y)),
                               __fmul_rn(z, z));
    const float qp = __fadd_rn(__fadd_rn(__fmul_rn(x, qx), __fmul_rn(y, qy)),
                               __fmul_rn(z, qz));
    const float d2 = __fsub_rn(__fadd_rn(q2, p2), __fmul_rn(2.0f, qp));
    return d2 < RADIUS2;
}

// ---------------------------------------------------------------------------
// Kernel 2: ball query + group. One warp per query point (b, s).
// Scan processes 128 points per iteration (4 per lane, vectorized float4 loads).
// Feature gather staged through a 32x33 smem tile, two 32-channel halves.
// ---------------------------------------------------------------------------
#define WARPS_PER_BLOCK 4

__global__ void __launch_bounds__(128) qag_kernel(const float* __restrict__ xyz,
                                                  const float* __restrict__ new_xyz,
                                                  float* __restrict__ out) {
    __shared__ int   sidx[WARPS_PER_BLOCK][NSAMPLE];
    __shared__ float tile[WARPS_PER_BLOCK][32 * 33];  // [c][k] padded, reused per half

    const int warp = threadIdx.x >> 5;
    const int lane = threadIdx.x & 31;
    const int q    = blockIdx.x * WARPS_PER_BLOCK + warp;   // global query id
    const int b    = q / SQ;
    const int s    = q % SQ;

    const float* nq = new_xyz + ((size_t)b * SQ + s) * 3;
    const float qx = nq[0], qy = nq[1], qz = nq[2];
    const float q2 = __fadd_rn(__fadd_rn(__fmul_rn(qx, qx), __fmul_rn(qy, qy)),
                               __fmul_rn(qz, qz));

    const float* px = xyz + (size_t)b * NPTS * 3;

    // ---------------- ball query: 128 points / iteration, early exit ---------
    int cnt = 0;
    const unsigned full = 0xffffffffu;
    const unsigned below = (1u << lane) - 1u;
    for (int base = 0; base < NPTS; base += 128) {
        // Lane loads 4 consecutive points (12 floats = 3 float4, contiguous).
        const float4* v = (const float4*)(px + (size_t)base * 3);
        const float4 A = v[3 * lane + 0];
        const float4 Bv = v[3 * lane + 1];
        const float4 Cv = v[3 * lane + 2];
        // points: P0=(A.x,A.y,A.z) P1=(A.w,Bv.x,Bv.y) P2=(Bv.z,Bv.w,Cv.x) P3=(Cv.y,Cv.z,Cv.w)
        unsigned m4 = 0;
        m4 |= (unsigned)in_ball(A.x,  A.y,  A.z,  qx, qy, qz, q2) << 0;
        m4 |= (unsigned)in_ball(A.w,  Bv.x, Bv.y, qx, qy, qz, q2) << 1;
        m4 |= (unsigned)in_ball(Bv.z, Bv.w, Cv.x, qx, qy, qz, q2) << 2;
        m4 |= (unsigned)in_ball(Cv.y, Cv.z, Cv.w, qx, qy, qz, q2) << 3;

        const unsigned b0 = __ballot_sync(full, m4 & 1u);
        const unsigned b1 = __ballot_sync(full, m4 & 2u);
        const unsigned b2 = __ballot_sync(full, m4 & 4u);
        const unsigned b3 = __ballot_sync(full, m4 & 8u);

        if (m4) {
            // count of in-ball points with smaller point index in lower lanes
            const int pre = __popc(b0 & below) + __popc(b1 & below)
                          + __popc(b2 & below) + __popc(b3 & below);
#pragma unroll
            for (int j = 0; j < 4; j++) {
                if ((m4 >> j) & 1u) {
                    const int slot = cnt + pre + __popc(m4 & ((1u << j) - 1u));
                    if (slot < NSAMPLE) sidx[warp][slot] = base + 4 * lane + j;
                }
            }
        }
        cnt += __popc(b0) + __popc(b1) + __popc(b2) + __popc(b3);  // warp-uniform
        if (cnt >= NSAMPLE) break;                                 // uniform branch
    }
    __syncwarp();

    // Pad with first index; all-zeros if no neighbor at all (matches reference).
    int myidx;
    if (cnt == 0) {
        myidx = 0;
    } else {
        const int c = cnt < NSAMPLE ? cnt : NSAMPLE;
        myidx = sidx[warp][lane < c ? lane : 0];
    }

    // ---------------- grouped_xyz: lane k handles neighbor k -----------------
    const size_t chs = (size_t)SQ * NSAMPLE;
    {
        const float x = px[myidx * 3 + 0];
        const float y = px[myidx * 3 + 1];
        const float z = px[myidx * 3 + 2];
        const size_t obase = ((size_t)b * CH_OUT) * chs + (size_t)s * NSAMPLE + lane;
        out[obase + 0 * chs] = x - qx;
        out[obase + 1 * chs] = y - qy;
        out[obase + 2 * chs] = z - qz;
    }

    // ---------------- grouped features: two 32-channel halves via smem tile --
    {
        float* t = tile[warp];
        const float* ft = g_featT + (size_t)b * NPTS * CF;
#pragma unroll
        for (int half = 0; half < 2; half++) {
#pragma unroll 8
            for (int k = 0; k < NSAMPLE; k++) {
                const int idxk = __shfl_sync(full, myidx, k);
                // coalesced 128B read of 32 contiguous channels; conflict-free store
                t[lane * 33 + k] = ft[(size_t)idxk * CF + half * 32 + lane];
            }
            __syncwarp();
            const size_t fbase = ((size_t)b * CH_OUT + 3 + half * 32) * chs
                               + (size_t)s * NSAMPLE + lane;
#pragma unroll 8
            for (int c = 0; c < 32; c++) {
                out[fbase + (size_t)c * chs] = t[c * 33 + lane];  // conflict-free
            }
            __syncwarp();  // tile reused next half
        }
    }
}

// ---------------------------------------------------------------------------
// Launch
// ---------------------------------------------------------------------------
extern "C" void kernel_launch(void* const* d_in, const int* in_sizes, int n_in,
                              void* d_out, int out_size) {
    const float* xyz      = (const float*)d_in[0];  // (B, N, 3)
    const float* new_xyz  = (const float*)d_in[1];  // (B, S, 3)
    const float* features = (const float*)d_in[2];  // (B, C, N)
    float*       out      = (float*)d_out;          // (B, 67, S, 32)

    (void)in_sizes; (void)n_in; (void)out_size;

    dim3 tgrid(NPTS / 32, CF / 32, BB);
    dim3 tblock(32, 8);
    transpose_feat_kernel<<<tgrid, tblock>>>(features);

    const int nquery = BB * SQ;                       // 8192
    const int blocks = nquery / WARPS_PER_BLOCK;      // 2048
    qag_kernel<<<blocks, WARPS_PER_BLOCK * 32>>>(xyz, new_xyz, out);
}